// round 1
// baseline (speedup 1.0000x reference)
#include <cuda_runtime.h>
#include <math.h>

#define NB 2
#define NM 2048
#define ND 1024
#define NH 16
#define NHD 64
#define NTOK (NB*NM)   // 4096

// ---- scratch (static device globals: allocation-free) ----
__device__ float g_q [NTOK*ND];
__device__ float g_k [NTOK*ND];
__device__ float g_v [NTOK*ND];
__device__ float g_qh[NTOK*ND];
__device__ float g_kh[NTOK*ND];
__device__ float g_vh[NTOK*ND];
__device__ float g_o [NTOK*ND];
__device__ float g_theta[ND/2];

// theta[p] = 10000^(-2(p-1)/1024), computed in double for accuracy, rounded to fp32
__global__ void init_theta_kernel() {
    int p = threadIdx.x;
    if (p < ND/2) {
        double e = -2.0 * ((double)p - 1.0) / (double)ND;
        g_theta[p] = (float)exp(e * log(10000.0));
    }
}

// ============================================================================
// GEMM: C[i,j] = sum_k A[i,k] * W[j,k]   (A: [4096,1024], W: [1024,1024] row-major)
// EPI: 1 = +bias, 2 = RoPE epilogue
// 128x128 tile, BK=16, 256 threads, 8x8 per thread
// ============================================================================
template<int EPI>
__global__ __launch_bounds__(256) void gemm_nt_kernel(
    const float* __restrict__ A, const float* __restrict__ W,
    const float* __restrict__ bias, float* __restrict__ C)
{
    __shared__ float As[16][132];
    __shared__ float Bs[16][132];
    const int tid = threadIdx.x;
    const int tx = tid & 15;
    const int ty = tid >> 4;
    const int m0 = blockIdx.y << 7;
    const int n0 = blockIdx.x << 7;

    float acc[8][8];
#pragma unroll
    for (int i = 0; i < 8; i++)
#pragma unroll
        for (int j = 0; j < 8; j++) acc[i][j] = 0.f;

    for (int k0 = 0; k0 < 1024; k0 += 16) {
#pragma unroll
        for (int t = 0; t < 2; t++) {
            int lin = tid + t * 256;
            int row = lin >> 2, c4 = lin & 3;
            float4 va = *(const float4*)(A + (size_t)(m0 + row) * 1024 + k0 + c4 * 4);
            As[c4*4+0][row] = va.x; As[c4*4+1][row] = va.y;
            As[c4*4+2][row] = va.z; As[c4*4+3][row] = va.w;
            float4 vb = *(const float4*)(W + (size_t)(n0 + row) * 1024 + k0 + c4 * 4);
            Bs[c4*4+0][row] = vb.x; Bs[c4*4+1][row] = vb.y;
            Bs[c4*4+2][row] = vb.z; Bs[c4*4+3][row] = vb.w;
        }
        __syncthreads();
#pragma unroll
        for (int kk = 0; kk < 16; kk++) {
            float a[8], b[8];
            *(float4*)&a[0] = *(const float4*)&As[kk][ty * 8];
            *(float4*)&a[4] = *(const float4*)&As[kk][ty * 8 + 4];
            *(float4*)&b[0] = *(const float4*)&Bs[kk][tx * 8];
            *(float4*)&b[4] = *(const float4*)&Bs[kk][tx * 8 + 4];
#pragma unroll
            for (int i = 0; i < 8; i++)
#pragma unroll
                for (int j = 0; j < 8; j++)
                    acc[i][j] = fmaf(a[i], b[j], acc[i][j]);
        }
        __syncthreads();
    }

    if (EPI == 1) {
        float bi[8];
#pragma unroll
        for (int j = 0; j < 8; j++) bi[j] = bias[n0 + tx * 8 + j];
#pragma unroll
        for (int i = 0; i < 8; i++) {
            int r = m0 + ty * 8 + i;
            float* crow = C + (size_t)r * 1024 + n0 + tx * 8;
#pragma unroll
            for (int j = 0; j < 8; j++) crow[j] = acc[i][j] + bi[j];
        }
    } else { // EPI == 2: RoPE
        float theta[4];
        const int p0 = (n0 >> 1) + tx * 4;
#pragma unroll
        for (int t = 0; t < 4; t++) theta[t] = g_theta[p0 + t];
#pragma unroll
        for (int i = 0; i < 8; i++) {
            int r = m0 + ty * 8 + i;
            float mm = (float)(r & (NM - 1));
            float* crow = C + (size_t)r * 1024 + n0 + tx * 8;
#pragma unroll
            for (int t = 0; t < 4; t++) {
                float sn, cn;
                sincosf(mm * theta[t], &sn, &cn);
                float xe = acc[i][2 * t], xo = acc[i][2 * t + 1];
                crow[2 * t]     =  xe * cn + xo * sn;
                crow[2 * t + 1] = -xe * sn + xo * cn;
            }
        }
    }
}

// ============================================================================
// Causal flash attention, fp32. Block = (b, h, 64-query tile), 256 threads.
// Per thread: 4x4 fragment of S / O. Online softmax. P staged through smem.
// ============================================================================
__global__ __launch_bounds__(256) void attn_kernel(
    const float* __restrict__ qh, const float* __restrict__ kh,
    const float* __restrict__ vh, float* __restrict__ o)
{
    const int LDT = 68;
    extern __shared__ float sm[];
    float* Qs = sm;
    float* Ks = sm + 64 * LDT;
    float* Vs = sm + 2 * 64 * LDT;
    float* Ps = sm + 3 * 64 * LDT;

    const int tid = threadIdx.x;
    const int tx = tid & 15, ty = tid >> 4;
    const int qi = blockIdx.x, h = blockIdx.y, b = blockIdx.z;
    const int q0 = qi * 64;

    const float* qb = qh + (size_t)b * NM * ND + (size_t)h * NHD;
    const float* kb = kh + (size_t)b * NM * ND + (size_t)h * NHD;
    const float* vb = vh + (size_t)b * NM * ND + (size_t)h * NHD;

    // Load Q tile, fold in 1/sqrt(hd) = 0.125
#pragma unroll
    for (int t = 0; t < 4; t++) {
        int lin = tid + t * 256;
        int row = lin >> 4, c4 = lin & 15;
        float4 v = *(const float4*)(qb + (size_t)(q0 + row) * ND + c4 * 4);
        v.x *= 0.125f; v.y *= 0.125f; v.z *= 0.125f; v.w *= 0.125f;
        *(float4*)&Qs[row * LDT + c4 * 4] = v;
    }

    float m_i[4], l_i[4], Oa[4][4];
#pragma unroll
    for (int i = 0; i < 4; i++) {
        m_i[i] = -INFINITY; l_i[i] = 0.f;
#pragma unroll
        for (int j = 0; j < 4; j++) Oa[i][j] = 0.f;
    }
    __syncthreads();

    for (int kt = 0; kt <= qi; kt++) {
        int k0 = kt * 64;
#pragma unroll
        for (int t = 0; t < 4; t++) {
            int lin = tid + t * 256;
            int row = lin >> 4, c4 = lin & 15;
            *(float4*)&Ks[row * LDT + c4 * 4] =
                *(const float4*)(kb + (size_t)(k0 + row) * ND + c4 * 4);
            *(float4*)&Vs[row * LDT + c4 * 4] =
                *(const float4*)(vb + (size_t)(k0 + row) * ND + c4 * 4);
        }
        __syncthreads();

        // S = Q K^T (4x4 per thread)
        float S[4][4];
#pragma unroll
        for (int i = 0; i < 4; i++)
#pragma unroll
            for (int j = 0; j < 4; j++) S[i][j] = 0.f;

        for (int k4 = 0; k4 < 16; k4++) {
            float qv[4][4], kv[4][4];
#pragma unroll
            for (int i = 0; i < 4; i++)
                *(float4*)qv[i] = *(const float4*)&Qs[(ty * 4 + i) * LDT + k4 * 4];
#pragma unroll
            for (int j = 0; j < 4; j++)
                *(float4*)kv[j] = *(const float4*)&Ks[(tx * 4 + j) * LDT + k4 * 4];
#pragma unroll
            for (int i = 0; i < 4; i++)
#pragma unroll
                for (int j = 0; j < 4; j++)
#pragma unroll
                    for (int kk = 0; kk < 4; kk++)
                        S[i][j] = fmaf(qv[i][kk], kv[j][kk], S[i][j]);
        }

        if (kt == qi) {
#pragma unroll
            for (int i = 0; i < 4; i++)
#pragma unroll
                for (int j = 0; j < 4; j++)
                    if (tx * 4 + j > ty * 4 + i) S[i][j] = -INFINITY;
        }

        // online softmax update (row = 16-lane group sharing ty)
#pragma unroll
        for (int i = 0; i < 4; i++) {
            float mx = fmaxf(fmaxf(S[i][0], S[i][1]), fmaxf(S[i][2], S[i][3]));
#pragma unroll
            for (int off = 8; off >= 1; off >>= 1)
                mx = fmaxf(mx, __shfl_xor_sync(0xffffffffu, mx, off));
            float mn = fmaxf(m_i[i], mx);
            float alpha = expf(m_i[i] - mn);
            float rs = 0.f;
#pragma unroll
            for (int j = 0; j < 4; j++) {
                float p = expf(S[i][j] - mn);
                S[i][j] = p; rs += p;
            }
#pragma unroll
            for (int off = 8; off >= 1; off >>= 1)
                rs += __shfl_xor_sync(0xffffffffu, rs, off);
            l_i[i] = l_i[i] * alpha + rs;
            m_i[i] = mn;
#pragma unroll
            for (int j = 0; j < 4; j++) Oa[i][j] *= alpha;
            float4 pv = make_float4(S[i][0], S[i][1], S[i][2], S[i][3]);
            *(float4*)&Ps[(ty * 4 + i) * LDT + tx * 4] = pv;
        }
        __syncthreads();

        // O += P V
        for (int k4 = 0; k4 < 16; k4++) {
            float pr[4][4], vr[4][4];
#pragma unroll
            for (int i = 0; i < 4; i++)
                *(float4*)pr[i] = *(const float4*)&Ps[(ty * 4 + i) * LDT + k4 * 4];
#pragma unroll
            for (int t = 0; t < 4; t++)
                *(float4*)vr[t] = *(const float4*)&Vs[(k4 * 4 + t) * LDT + tx * 4];
#pragma unroll
            for (int i = 0; i < 4; i++)
#pragma unroll
                for (int j = 0; j < 4; j++)
#pragma unroll
                    for (int t = 0; t < 4; t++)
                        Oa[i][j] = fmaf(pr[i][t], vr[t][j], Oa[i][j]);
        }
        __syncthreads();
    }

    float* obp = o + (size_t)b * NM * ND + (size_t)h * NHD;
#pragma unroll
    for (int i = 0; i < 4; i++) {
        float inv = 1.f / l_i[i];
        int r = q0 + ty * 4 + i;
#pragma unroll
        for (int j = 0; j < 4; j++)
            obp[(size_t)r * ND + tx * 4 + j] = Oa[i][j] * inv;
    }
}

// ============================================================================
extern "C" void kernel_launch(void* const* d_in, const int* in_sizes, int n_in,
                              void* d_out, int out_size)
{
    const float* x   = (const float*)d_in[0];
    const float* wq  = (const float*)d_in[1];
    const float* wk  = (const float*)d_in[2];
    const float* wv  = (const float*)d_in[3];
    const float* ipw = (const float*)d_in[4];
    const float* ipb = (const float*)d_in[5];
    const float* ow  = (const float*)d_in[6];
    const float* ob  = (const float*)d_in[7];
    float* out = (float*)d_out;

    float *q, *k, *v, *qh, *kh, *vh, *o;
    cudaGetSymbolAddress((void**)&q,  g_q);
    cudaGetSymbolAddress((void**)&k,  g_k);
    cudaGetSymbolAddress((void**)&v,  g_v);
    cudaGetSymbolAddress((void**)&qh, g_qh);
    cudaGetSymbolAddress((void**)&kh, g_kh);
    cudaGetSymbolAddress((void**)&vh, g_vh);
    cudaGetSymbolAddress((void**)&o,  g_o);

    const int attn_smem = 4 * 64 * 68 * 4; // 69632 bytes
    cudaFuncSetAttribute(attn_kernel,
                         cudaFuncAttributeMaxDynamicSharedMemorySize, attn_smem);

    init_theta_kernel<<<1, 512>>>();

    dim3 gb(8, 32), tb(256);
    // QKV projections with fused RoPE epilogue
    gemm_nt_kernel<2><<<gb, tb>>>(x, wq, nullptr, q);
    gemm_nt_kernel<2><<<gb, tb>>>(x, wk, nullptr, k);
    gemm_nt_kernel<2><<<gb, tb>>>(x, wv, nullptr, v);
    // in_proj (bias fused)
    gemm_nt_kernel<1><<<gb, tb>>>(q, ipw,                 ipb,        qh);
    gemm_nt_kernel<1><<<gb, tb>>>(k, ipw + 1024 * 1024,   ipb + 1024, kh);
    gemm_nt_kernel<1><<<gb, tb>>>(v, ipw + 2 * 1024 * 1024, ipb + 2048, vh);
    // causal flash attention
    attn_kernel<<<dim3(NM / 64, NH, NB), 256, attn_smem>>>(qh, kh, vh, o);
    // output projection (bias fused)
    gemm_nt_kernel<1><<<gb, tb>>>(o, ow, ob, out);
}

// round 2
// speedup vs baseline: 3.4693x; 3.4693x over previous
#include <cuda_runtime.h>
#include <math.h>
#include <stdint.h>

#define NB 2
#define NM 2048
#define ND 1024
#define NH 16
#define NHD 64
#define NTOK (NB*NM)   // 4096

// ---- scratch (static device globals: allocation-free) ----
__device__ float g_q [NTOK*ND];
__device__ float g_k [NTOK*ND];
__device__ float g_v [NTOK*ND];
__device__ float g_qh[NTOK*ND];
__device__ float g_kh[NTOK*ND];
__device__ float g_vh[NTOK*ND];
__device__ float g_o [NTOK*ND];
__device__ float g_theta[ND/2];

// theta[p] = 10000^(-2(p-1)/1024) in double, rounded to fp32
__global__ void init_theta_kernel() {
    int p = threadIdx.x;
    if (p < ND/2) {
        double e = -2.0 * ((double)p - 1.0) / (double)ND;
        g_theta[p] = (float)exp(e * log(10000.0));
    }
}

// ---------------------------------------------------------------------------
// helpers: tf32 convert, m16n8k8 mma, cp.async
// ---------------------------------------------------------------------------
__device__ __forceinline__ uint32_t f2tf(float f) {
    uint32_t r;
    asm("cvt.rna.tf32.f32 %0, %1;" : "=r"(r) : "f"(f));
    return r;
}

__device__ __forceinline__ void mma_tf32(float* d, const uint32_t* a, const uint32_t* b) {
    asm volatile(
        "mma.sync.aligned.m16n8k8.row.col.f32.tf32.tf32.f32 "
        "{%0,%1,%2,%3}, {%4,%5,%6,%7}, {%8,%9}, {%0,%1,%2,%3};"
        : "+f"(d[0]), "+f"(d[1]), "+f"(d[2]), "+f"(d[3])
        : "r"(a[0]), "r"(a[1]), "r"(a[2]), "r"(a[3]), "r"(b[0]), "r"(b[1]));
}

__device__ __forceinline__ void cp_async16(void* smem, const void* gmem) {
    uint32_t s = (uint32_t)__cvta_generic_to_shared(smem);
    asm volatile("cp.async.cg.shared.global [%0], [%1], 16;" :: "r"(s), "l"(gmem));
}
__device__ __forceinline__ void cp_commit() { asm volatile("cp.async.commit_group;"); }
template<int N> __device__ __forceinline__ void cp_wait() {
    asm volatile("cp.async.wait_group %0;" :: "n"(N));
}

// ===========================================================================
// TF32 GEMM: C[i,j] = sum_k A[i,k]*W[j,k]. A:[4096,1024], W:[1024,1024].
// 128x128 tile, BK=32, 256 threads (8 warps, 2x4 -> 64x32 warp tiles).
// EPI: 1 = +bias, 2 = RoPE epilogue.
// ===========================================================================
#define GLD 36          // padded smem row stride (floats), 16B multiple
#define NKB 32          // 1024 / 32

template<int EPI>
__global__ __launch_bounds__(256) void gemm_tf32_kernel(
    const float* __restrict__ A, const float* __restrict__ W,
    const float* __restrict__ bias, float* __restrict__ C)
{
    extern __shared__ float smw[];
    float* As = smw;                    // [2][128*GLD]
    float* Bs = smw + 2 * 128 * GLD;    // [2][128*GLD]

    const int tid  = threadIdx.x;
    const int lane = tid & 31, warp = tid >> 5;
    const int g = lane >> 2, tig = lane & 3;
    const int wm = (warp & 1) * 64, wn = (warp >> 1) * 32;
    const int m0 = blockIdx.y << 7, n0 = blockIdx.x << 7;

    const int lrow = tid >> 3;
    const int lc4  = (tid & 7) * 4;

    float acc[4][4][4];
#pragma unroll
    for (int mf = 0; mf < 4; mf++)
#pragma unroll
        for (int nf = 0; nf < 4; nf++)
#pragma unroll
            for (int t = 0; t < 4; t++) acc[mf][nf][t] = 0.f;

    auto issue = [&](int kb, int buf) {
        const float* Ab = A + (size_t)m0 * 1024 + kb * 32 + lc4;
        const float* Wb = W + (size_t)n0 * 1024 + kb * 32 + lc4;
        float* Asb = As + buf * 128 * GLD;
        float* Bsb = Bs + buf * 128 * GLD;
#pragma unroll
        for (int i = 0; i < 4; i++) {
            int r = lrow + i * 32;
            cp_async16(Asb + r * GLD + lc4, Ab + (size_t)r * 1024);
            cp_async16(Bsb + r * GLD + lc4, Wb + (size_t)r * 1024);
        }
    };

    issue(0, 0); cp_commit();
    int buf = 0;
    for (int kb = 0; kb < NKB; kb++) {
        if (kb + 1 < NKB) { issue(kb + 1, buf ^ 1); cp_commit(); cp_wait<1>(); }
        else              { cp_wait<0>(); }
        __syncthreads();

        const float* Asb = As + buf * 128 * GLD;
        const float* Bsb = Bs + buf * 128 * GLD;
#pragma unroll
        for (int s = 0; s < 4; s++) {
            uint32_t af[4][4], bf[4][2];
#pragma unroll
            for (int mf = 0; mf < 4; mf++) {
                const float* p = Asb + (wm + mf * 16 + g) * GLD + s * 8 + tig;
                af[mf][0] = f2tf(p[0]);
                af[mf][1] = f2tf(p[8 * GLD]);
                af[mf][2] = f2tf(p[4]);
                af[mf][3] = f2tf(p[8 * GLD + 4]);
            }
#pragma unroll
            for (int nf = 0; nf < 4; nf++) {
                const float* p = Bsb + (wn + nf * 8 + g) * GLD + s * 8 + tig;
                bf[nf][0] = f2tf(p[0]);
                bf[nf][1] = f2tf(p[4]);
            }
#pragma unroll
            for (int mf = 0; mf < 4; mf++)
#pragma unroll
                for (int nf = 0; nf < 4; nf++)
                    mma_tf32(acc[mf][nf], af[mf], bf[nf]);
        }
        __syncthreads();
        buf ^= 1;
    }

    if (EPI == 1) {
#pragma unroll
        for (int nf = 0; nf < 4; nf++) {
            int col = n0 + wn + nf * 8 + 2 * tig;
            float2 bv = *(const float2*)(bias + col);
#pragma unroll
            for (int mf = 0; mf < 4; mf++) {
                int r0 = m0 + wm + mf * 16 + g;
                float2 v0 = { acc[mf][nf][0] + bv.x, acc[mf][nf][1] + bv.y };
                float2 v1 = { acc[mf][nf][2] + bv.x, acc[mf][nf][3] + bv.y };
                *(float2*)(C + (size_t)r0 * 1024 + col)       = v0;
                *(float2*)(C + (size_t)(r0 + 8) * 1024 + col) = v1;
            }
        }
    } else { // RoPE: c0/c1 are the (even,odd) pair
#pragma unroll
        for (int nf = 0; nf < 4; nf++) {
            int col = n0 + wn + nf * 8 + 2 * tig;
            float th = g_theta[col >> 1];
#pragma unroll
            for (int mf = 0; mf < 4; mf++) {
                int r0 = m0 + wm + mf * 16 + g;
                {
                    float sn, cn;
                    sincosf((float)(r0 & (NM - 1)) * th, &sn, &cn);
                    float xe = acc[mf][nf][0], xo = acc[mf][nf][1];
                    float2 v = { xe * cn + xo * sn, -xe * sn + xo * cn };
                    *(float2*)(C + (size_t)r0 * 1024 + col) = v;
                }
                {
                    int r1 = r0 + 8;
                    float sn, cn;
                    sincosf((float)(r1 & (NM - 1)) * th, &sn, &cn);
                    float xe = acc[mf][nf][2], xo = acc[mf][nf][3];
                    float2 v = { xe * cn + xo * sn, -xe * sn + xo * cn };
                    *(float2*)(C + (size_t)r1 * 1024 + col) = v;
                }
            }
        }
    }
}

// ===========================================================================
// Causal flash attention, tf32 mma. Block = (64-query tile, h, b), 128 thr.
// Each warp owns 16 query rows. S: m16 x n64 x k64, O += P.V: m16 x n64 x k64.
// ===========================================================================
#define ALDT 68

__global__ __launch_bounds__(128) void attn_tf32_kernel(
    const float* __restrict__ qh, const float* __restrict__ kh,
    const float* __restrict__ vh, float* __restrict__ o)
{
    extern __shared__ float sm[];
    float* Qs = sm;
    float* Ks = sm + 64 * ALDT;
    float* Vs = sm + 2 * 64 * ALDT;
    float* Ps = sm + 3 * 64 * ALDT;

    const int tid  = threadIdx.x;
    const int lane = tid & 31, warp = tid >> 5;
    const int g = lane >> 2, tig = lane & 3;
    const int qi = blockIdx.x, h = blockIdx.y, b = blockIdx.z;
    const int q0 = qi * 64;

    const float* qb = qh + (size_t)b * NM * ND + h * NHD;
    const float* kb = kh + (size_t)b * NM * ND + h * NHD;
    const float* vb = vh + (size_t)b * NM * ND + h * NHD;

    // Q tile, fold in 1/sqrt(hd) = 0.125
#pragma unroll
    for (int t = 0; t < 8; t++) {
        int lin = tid + t * 128;
        int row = lin >> 4, c4 = (lin & 15) * 4;
        float4 v = *(const float4*)(qb + (size_t)(q0 + row) * ND + c4);
        v.x *= 0.125f; v.y *= 0.125f; v.z *= 0.125f; v.w *= 0.125f;
        *(float4*)&Qs[row * ALDT + c4] = v;
    }

    float m_i[2] = { -INFINITY, -INFINITY };
    float l_i[2] = { 0.f, 0.f };
    float Oa[8][4];
#pragma unroll
    for (int nf = 0; nf < 8; nf++)
#pragma unroll
        for (int t = 0; t < 4; t++) Oa[nf][t] = 0.f;
    __syncthreads();

    for (int kt = 0; kt <= qi; kt++) {
        int k0 = kt * 64;
#pragma unroll
        for (int t = 0; t < 8; t++) {
            int lin = tid + t * 128;
            int row = lin >> 4, c4 = (lin & 15) * 4;
            *(float4*)&Ks[row * ALDT + c4] =
                *(const float4*)(kb + (size_t)(k0 + row) * ND + c4);
            *(float4*)&Vs[row * ALDT + c4] =
                *(const float4*)(vb + (size_t)(k0 + row) * ND + c4);
        }
        __syncthreads();

        // S = Q K^T
        float S[8][4];
#pragma unroll
        for (int nf = 0; nf < 8; nf++)
#pragma unroll
            for (int t = 0; t < 4; t++) S[nf][t] = 0.f;

#pragma unroll
        for (int s = 0; s < 8; s++) {
            uint32_t af[4];
            const float* p = Qs + (warp * 16 + g) * ALDT + s * 8 + tig;
            af[0] = f2tf(p[0]);
            af[1] = f2tf(p[8 * ALDT]);
            af[2] = f2tf(p[4]);
            af[3] = f2tf(p[8 * ALDT + 4]);
#pragma unroll
            for (int nf = 0; nf < 8; nf++) {
                const float* pb = Ks + (nf * 8 + g) * ALDT + s * 8 + tig;
                uint32_t bf[2] = { f2tf(pb[0]), f2tf(pb[4]) };
                mma_tf32(S[nf], af, bf);
            }
        }

        if (kt == qi) {   // diagonal tile: causal mask (local col > local row)
#pragma unroll
            for (int nf = 0; nf < 8; nf++) {
                int c  = nf * 8 + 2 * tig;
                int r0 = warp * 16 + g, r1 = r0 + 8;
                if (c     > r0) S[nf][0] = -INFINITY;
                if (c + 1 > r0) S[nf][1] = -INFINITY;
                if (c     > r1) S[nf][2] = -INFINITY;
                if (c + 1 > r1) S[nf][3] = -INFINITY;
            }
        }

        // online softmax per row (rows g and g+8; 4 lanes per row -> xor 1,2)
#pragma unroll
        for (int r = 0; r < 2; r++) {
            float mx = -INFINITY;
#pragma unroll
            for (int nf = 0; nf < 8; nf++)
                mx = fmaxf(mx, fmaxf(S[nf][2 * r], S[nf][2 * r + 1]));
            mx = fmaxf(mx, __shfl_xor_sync(0xffffffffu, mx, 1));
            mx = fmaxf(mx, __shfl_xor_sync(0xffffffffu, mx, 2));
            float mn = fmaxf(m_i[r], mx);
            float alpha = __expf(m_i[r] - mn);
            float rs = 0.f;
#pragma unroll
            for (int nf = 0; nf < 8; nf++) {
                float p0 = __expf(S[nf][2 * r] - mn);
                float p1 = __expf(S[nf][2 * r + 1] - mn);
                S[nf][2 * r] = p0; S[nf][2 * r + 1] = p1;
                rs += p0 + p1;
            }
            rs += __shfl_xor_sync(0xffffffffu, rs, 1);
            rs += __shfl_xor_sync(0xffffffffu, rs, 2);
            l_i[r] = l_i[r] * alpha + rs;
            m_i[r] = mn;
#pragma unroll
            for (int nf = 0; nf < 8; nf++) {
                Oa[nf][2 * r]     *= alpha;
                Oa[nf][2 * r + 1] *= alpha;
            }
        }

        // stage P (each warp writes only its own 16 rows)
#pragma unroll
        for (int nf = 0; nf < 8; nf++) {
            float2 v0 = { S[nf][0], S[nf][1] };
            float2 v1 = { S[nf][2], S[nf][3] };
            *(float2*)&Ps[(warp * 16 + g) * ALDT + nf * 8 + 2 * tig]     = v0;
            *(float2*)&Ps[(warp * 16 + g + 8) * ALDT + nf * 8 + 2 * tig] = v1;
        }
        __syncwarp();

        // O += P V
#pragma unroll
        for (int s = 0; s < 8; s++) {
            uint32_t af[4];
            const float* p = Ps + (warp * 16 + g) * ALDT + s * 8 + tig;
            af[0] = f2tf(p[0]);
            af[1] = f2tf(p[8 * ALDT]);
            af[2] = f2tf(p[4]);
            af[3] = f2tf(p[8 * ALDT + 4]);
#pragma unroll
            for (int nf = 0; nf < 8; nf++) {
                const float* pv = Vs + (s * 8 + tig) * ALDT + nf * 8 + g;
                uint32_t bf[2] = { f2tf(pv[0]), f2tf(pv[4 * ALDT]) };
                mma_tf32(Oa[nf], af, bf);
            }
        }
        __syncthreads();
    }

    float* ob = o + (size_t)b * NM * ND + h * NHD;
#pragma unroll
    for (int r = 0; r < 2; r++) {
        float inv = 1.f / l_i[r];
        int row = q0 + warp * 16 + g + r * 8;
#pragma unroll
        for (int nf = 0; nf < 8; nf++) {
            float2 v2 = { Oa[nf][2 * r] * inv, Oa[nf][2 * r + 1] * inv };
            *(float2*)(ob + (size_t)row * ND + nf * 8 + 2 * tig) = v2;
        }
    }
}

// ===========================================================================
extern "C" void kernel_launch(void* const* d_in, const int* in_sizes, int n_in,
                              void* d_out, int out_size)
{
    const float* x   = (const float*)d_in[0];
    const float* wq  = (const float*)d_in[1];
    const float* wk  = (const float*)d_in[2];
    const float* wv  = (const float*)d_in[3];
    const float* ipw = (const float*)d_in[4];
    const float* ipb = (const float*)d_in[5];
    const float* ow  = (const float*)d_in[6];
    const float* ob  = (const float*)d_in[7];
    float* out = (float*)d_out;

    float *q, *k, *v, *qh, *kh, *vh, *o;
    cudaGetSymbolAddress((void**)&q,  g_q);
    cudaGetSymbolAddress((void**)&k,  g_k);
    cudaGetSymbolAddress((void**)&v,  g_v);
    cudaGetSymbolAddress((void**)&qh, g_qh);
    cudaGetSymbolAddress((void**)&kh, g_kh);
    cudaGetSymbolAddress((void**)&vh, g_vh);
    cudaGetSymbolAddress((void**)&o,  g_o);

    const int gemm_smem = 2 * 2 * 128 * GLD * 4;       // 73728
    const int attn_smem = 4 * 64 * ALDT * 4;           // 69632
    cudaFuncSetAttribute(gemm_tf32_kernel<1>,
                         cudaFuncAttributeMaxDynamicSharedMemorySize, gemm_smem);
    cudaFuncSetAttribute(gemm_tf32_kernel<2>,
                         cudaFuncAttributeMaxDynamicSharedMemorySize, gemm_smem);
    cudaFuncSetAttribute(attn_tf32_kernel,
                         cudaFuncAttributeMaxDynamicSharedMemorySize, attn_smem);

    init_theta_kernel<<<1, 512>>>();

    dim3 gb(8, 32), tb(256);
    // QKV projections with fused RoPE epilogue
    gemm_tf32_kernel<2><<<gb, tb, gemm_smem>>>(x, wq, nullptr, q);
    gemm_tf32_kernel<2><<<gb, tb, gemm_smem>>>(x, wk, nullptr, k);
    gemm_tf32_kernel<2><<<gb, tb, gemm_smem>>>(x, wv, nullptr, v);
    // in_proj (bias fused)
    gemm_tf32_kernel<1><<<gb, tb, gemm_smem>>>(q, ipw,                   ipb,        qh);
    gemm_tf32_kernel<1><<<gb, tb, gemm_smem>>>(k, ipw + 1024 * 1024,     ipb + 1024, kh);
    gemm_tf32_kernel<1><<<gb, tb, gemm_smem>>>(v, ipw + 2 * 1024 * 1024, ipb + 2048, vh);
    // causal flash attention
    attn_tf32_kernel<<<dim3(NM / 64, NH, NB), 128, attn_smem>>>(qh, kh, vh, o);
    // output projection (bias fused)
    gemm_tf32_kernel<1><<<gb, tb, gemm_smem>>>(o, ow, ob, out);
}

// round 3
// speedup vs baseline: 7.3962x; 2.1319x over previous
#include <cuda_runtime.h>
#include <cuda_fp16.h>
#include <math.h>
#include <stdint.h>

#define NB 2
#define NM 2048
#define ND 1024
#define NH 16
#define NHD 64
#define NTOK (NB*NM)   // 4096

// ---- fp16 scratch (static device globals: allocation-free) ----
__device__ __half h_x [NTOK*ND];
__device__ __half h_wq[ND*ND];
__device__ __half h_wk[ND*ND];
__device__ __half h_wv[ND*ND];
__device__ __half h_ipw[3*ND*ND];
__device__ __half h_ow[ND*ND];
__device__ __half h_q [NTOK*ND];
__device__ __half h_k [NTOK*ND];
__device__ __half h_v [NTOK*ND];
__device__ __half h_qh[NTOK*ND];
__device__ __half h_kh[NTOK*ND];
__device__ __half h_vh[NTOK*ND];
__device__ __half h_o [NTOK*ND];
__device__ float  g_theta[ND/2];

__global__ void init_theta_kernel() {
    int p = threadIdx.x;
    if (p < ND/2) {
        double e = -2.0 * ((double)p - 1.0) / (double)ND;
        g_theta[p] = (float)exp(e * log(10000.0));
    }
}

// float -> half bulk convert (8 elems / thread)
__global__ void f2h_kernel(const float4* __restrict__ in, uint2* __restrict__ out, int n8) {
    int i = blockIdx.x * blockDim.x + threadIdx.x;
    if (i < n8) {
        float4 a = in[2*i], b = in[2*i+1];
        __half2 h0 = __floats2half2_rn(a.x, a.y);
        __half2 h1 = __floats2half2_rn(a.z, a.w);
        __half2 h2 = __floats2half2_rn(b.x, b.y);
        __half2 h3 = __floats2half2_rn(b.z, b.w);
        out[2*i]   = make_uint2(*(uint32_t*)&h0, *(uint32_t*)&h1);
        out[2*i+1] = make_uint2(*(uint32_t*)&h2, *(uint32_t*)&h3);
    }
}

// ---------------------------------------------------------------------------
// helpers
// ---------------------------------------------------------------------------
__device__ __forceinline__ uint32_t sptr(const void* p) {
    return (uint32_t)__cvta_generic_to_shared(p);
}
__device__ __forceinline__ void ldsm_x4(uint32_t* r, uint32_t a) {
    asm volatile("ldmatrix.sync.aligned.m8n8.x4.shared.b16 {%0,%1,%2,%3}, [%4];"
        : "=r"(r[0]), "=r"(r[1]), "=r"(r[2]), "=r"(r[3]) : "r"(a));
}
__device__ __forceinline__ void ldsm_x4t(uint32_t* r, uint32_t a) {
    asm volatile("ldmatrix.sync.aligned.m8n8.x4.trans.shared.b16 {%0,%1,%2,%3}, [%4];"
        : "=r"(r[0]), "=r"(r[1]), "=r"(r[2]), "=r"(r[3]) : "r"(a));
}
__device__ __forceinline__ void mma_f16(float* d, const uint32_t* a, uint32_t b0, uint32_t b1) {
    asm volatile(
        "mma.sync.aligned.m16n8k16.row.col.f32.f16.f16.f32 "
        "{%0,%1,%2,%3}, {%4,%5,%6,%7}, {%8,%9}, {%0,%1,%2,%3};"
        : "+f"(d[0]), "+f"(d[1]), "+f"(d[2]), "+f"(d[3])
        : "r"(a[0]), "r"(a[1]), "r"(a[2]), "r"(a[3]), "r"(b0), "r"(b1));
}
__device__ __forceinline__ void cp_async16(void* smem, const void* gmem) {
    asm volatile("cp.async.cg.shared.global [%0], [%1], 16;" :: "r"(sptr(smem)), "l"(gmem));
}
__device__ __forceinline__ void cp_commit() { asm volatile("cp.async.commit_group;"); }
template<int N> __device__ __forceinline__ void cp_wait() {
    asm volatile("cp.async.wait_group %0;" :: "n"(N));
}

// ===========================================================================
// FP16 GEMM: C[i,j] = sum_k A[i,k]*W[j,k]. A:[4096,1024], W:[1024,1024] fp16.
// 128x128 tile, BK=64, 256 threads (8 warps: 2x4 -> 64x32 warp tiles).
// EPI: 1 = (+bias)*scale -> fp16, 2 = RoPE -> fp16, 3 = +bias -> fp32.
// ===========================================================================
#define GLD 72          // padded smem row stride in halves (144B, 16B multiple)
#define NKB 16          // 1024 / 64

template<int EPI>
__global__ __launch_bounds__(256) void gemm_f16_kernel(
    const __half* __restrict__ A, const __half* __restrict__ W,
    const float* __restrict__ bias, __half* __restrict__ Ch,
    float* __restrict__ Cf, float scale)
{
    extern __shared__ __half smh[];
    __half* As = smh;                    // [2][128*GLD]
    __half* Bs = smh + 2 * 128 * GLD;

    const int tid  = threadIdx.x;
    const int lane = tid & 31, warp = tid >> 5;
    const int g = lane >> 2, tig = lane & 3;
    const int wm = (warp & 1) * 64, wn = (warp >> 1) * 32;
    const int m0 = blockIdx.y << 7, n0 = blockIdx.x << 7;

    const int lrow = tid >> 3;           // 0..31 (x4 iters -> 128 rows)
    const int lch  = (tid & 7) * 8;      // half offset of 16B chunk

    float acc[4][4][4];
#pragma unroll
    for (int mf = 0; mf < 4; mf++)
#pragma unroll
        for (int nf = 0; nf < 4; nf++)
#pragma unroll
            for (int t = 0; t < 4; t++) acc[mf][nf][t] = 0.f;

    auto issue = [&](int kb, int buf) {
        const __half* Ab = A + (size_t)m0 * 1024 + kb * 64 + lch;
        const __half* Wb = W + (size_t)n0 * 1024 + kb * 64 + lch;
        __half* Asb = As + buf * 128 * GLD;
        __half* Bsb = Bs + buf * 128 * GLD;
#pragma unroll
        for (int i = 0; i < 4; i++) {
            int r = lrow + i * 32;
            cp_async16(Asb + r * GLD + lch, Ab + (size_t)r * 1024);
            cp_async16(Bsb + r * GLD + lch, Wb + (size_t)r * 1024);
        }
    };

    // ldmatrix lane addressing
    const int a_row = lane & 15;                 // + wm + mf*16
    const int a_col = (lane & 16) >> 1;          // 0 or 8
    const int b_row = (lane & 7) + (lane & 8);   // 0..15 within 16-row pair
    const int b_col = (lane & 16) >> 1;          // k offset select... (see below)

    issue(0, 0); cp_commit();
    int buf = 0;
    for (int kb = 0; kb < NKB; kb++) {
        if (kb + 1 < NKB) { issue(kb + 1, buf ^ 1); cp_commit(); cp_wait<1>(); }
        else              { cp_wait<0>(); }
        __syncthreads();

        const __half* Asb = As + buf * 128 * GLD;
        const __half* Bsb = Bs + buf * 128 * GLD;
#pragma unroll
        for (int s = 0; s < 4; s++) {
            uint32_t af[4][4];
#pragma unroll
            for (int mf = 0; mf < 4; mf++)
                ldsm_x4(af[mf], sptr(Asb + (wm + mf * 16 + a_row) * GLD + s * 16 + a_col));
            // B: x4 covers two n-frags (16 rows), tiles [nf0 kl, nf0 kh, nf1 kl, nf1 kh]
            uint32_t bf[2][4];
#pragma unroll
            for (int np = 0; np < 2; np++) {
                // lanes 0-15: rows 0-15 (nf pair low+high via lane&8 -> k offset)
                // addressing: row = np*16*? ... rows: (lane&7) + ((lane&16)>>1)? use:
                // tiles: t0 rows nfE(8) kl, t1 rows nfE kh, t2 rows nfO kl, t3 rows nfO kh
                int row = wn + np * 16 + (lane & 7) + ((lane & 16) >> 1);
                int col = s * 16 + (lane & 8);
                ldsm_x4(bf[np], sptr(Bsb + row * GLD + col));
            }
#pragma unroll
            for (int mf = 0; mf < 4; mf++)
#pragma unroll
                for (int np = 0; np < 2; np++) {
                    mma_f16(acc[mf][np * 2],     af[mf], bf[np][0], bf[np][1]);
                    mma_f16(acc[mf][np * 2 + 1], af[mf], bf[np][2], bf[np][3]);
                }
        }
        __syncthreads();
        buf ^= 1;
    }

    if (EPI == 1) {        // (+bias) * scale -> fp16
#pragma unroll
        for (int nf = 0; nf < 4; nf++) {
            int col = n0 + wn + nf * 8 + 2 * tig;
            float2 bv = *(const float2*)(bias + col);
#pragma unroll
            for (int mf = 0; mf < 4; mf++) {
                int r0 = m0 + wm + mf * 16 + g;
                __half2 v0 = __floats2half2_rn((acc[mf][nf][0] + bv.x) * scale,
                                               (acc[mf][nf][1] + bv.y) * scale);
                __half2 v1 = __floats2half2_rn((acc[mf][nf][2] + bv.x) * scale,
                                               (acc[mf][nf][3] + bv.y) * scale);
                *(__half2*)(Ch + (size_t)r0 * 1024 + col)       = v0;
                *(__half2*)(Ch + (size_t)(r0 + 8) * 1024 + col) = v1;
            }
        }
    } else if (EPI == 2) { // RoPE -> fp16 (c0/c1 = even/odd pair)
#pragma unroll
        for (int nf = 0; nf < 4; nf++) {
            int col = n0 + wn + nf * 8 + 2 * tig;
            float th = g_theta[col >> 1];
#pragma unroll
            for (int mf = 0; mf < 4; mf++) {
                int r0 = m0 + wm + mf * 16 + g;
#pragma unroll
                for (int hlf = 0; hlf < 2; hlf++) {
                    int r = r0 + hlf * 8;
                    float sn, cn;
                    sincosf((float)(r & (NM - 1)) * th, &sn, &cn);
                    float xe = acc[mf][nf][2 * hlf], xo = acc[mf][nf][2 * hlf + 1];
                    *(__half2*)(Ch + (size_t)r * 1024 + col) =
                        __floats2half2_rn(xe * cn + xo * sn, -xe * sn + xo * cn);
                }
            }
        }
    } else {               // +bias -> fp32
#pragma unroll
        for (int nf = 0; nf < 4; nf++) {
            int col = n0 + wn + nf * 8 + 2 * tig;
            float2 bv = *(const float2*)(bias + col);
#pragma unroll
            for (int mf = 0; mf < 4; mf++) {
                int r0 = m0 + wm + mf * 16 + g;
                float2 v0 = { acc[mf][nf][0] + bv.x, acc[mf][nf][1] + bv.y };
                float2 v1 = { acc[mf][nf][2] + bv.x, acc[mf][nf][3] + bv.y };
                *(float2*)(Cf + (size_t)r0 * 1024 + col)       = v0;
                *(float2*)(Cf + (size_t)(r0 + 8) * 1024 + col) = v1;
            }
        }
    }
}

// ===========================================================================
// Causal flash attention, fp16 mma. Block = (64-q tile, h, b), 128 threads.
// Warp owns 16 q rows. smem tiles stride 72 halves. cp.async double-buffer K/V.
// 1/sqrt(hd) pre-folded into qh.
// ===========================================================================
#define ATD 72
#define QOFF 0
#define KOFF (64*ATD)            // 2 buffers
#define VOFF (3*64*ATD)          // 2 buffers
#define POFF (5*64*ATD)
#define ASM_TOT (6*64*ATD*2)     // bytes

__global__ __launch_bounds__(128) void attn_f16_kernel(
    const __half* __restrict__ qh, const __half* __restrict__ kh,
    const __half* __restrict__ vh, __half* __restrict__ o)
{
    extern __shared__ __half sm[];
    __half* Qs = sm + QOFF;
    __half* Ks = sm + KOFF;
    __half* Vs = sm + VOFF;
    __half* Ps = sm + POFF;

    const int tid  = threadIdx.x;
    const int lane = tid & 31, warp = tid >> 5;
    const int g = lane >> 2, tig = lane & 3;
    const int qi = blockIdx.x, h = blockIdx.y, b = blockIdx.z;
    const int q0 = qi * 64;

    const __half* qb = qh + (size_t)b * NM * ND + h * NHD;
    const __half* kb = kh + (size_t)b * NM * ND + h * NHD;
    const __half* vb = vh + (size_t)b * NM * ND + h * NHD;

    const int lrow = tid >> 3;       // 0..15, x4 -> 64 rows
    const int lch  = (tid & 7) * 8;

    // Q tile (already scaled by 0.125 upstream)
#pragma unroll
    for (int i = 0; i < 4; i++) {
        int r = lrow + i * 16;
        cp_async16(Qs + r * ATD + lch, qb + (size_t)(q0 + r) * ND + lch);
    }

    auto issue_kv = [&](int kt, int bufb) {
        int k0 = kt * 64;
        __half* Kd = Ks + bufb * 64 * ATD;
        __half* Vd = Vs + bufb * 64 * ATD;
#pragma unroll
        for (int i = 0; i < 4; i++) {
            int r = lrow + i * 16;
            cp_async16(Kd + r * ATD + lch, kb + (size_t)(k0 + r) * ND + lch);
            cp_async16(Vd + r * ATD + lch, vb + (size_t)(k0 + r) * ND + lch);
        }
    };

    float m_i[2] = { -INFINITY, -INFINITY };
    float l_i[2] = { 0.f, 0.f };
    float Oa[8][4];
#pragma unroll
    for (int nf = 0; nf < 8; nf++)
#pragma unroll
        for (int t = 0; t < 4; t++) Oa[nf][t] = 0.f;

    issue_kv(0, 0); cp_commit();
    int buf = 0;

    const int a_row = lane & 15;
    const int a_col = (lane & 16) >> 1;

    for (int kt = 0; kt <= qi; kt++) {
        if (kt + 1 <= qi) { issue_kv(kt + 1, buf ^ 1); cp_commit(); cp_wait<1>(); }
        else              { cp_wait<0>(); }
        __syncthreads();

        const __half* Kb = Ks + buf * 64 * ATD;
        const __half* Vb = Vs + buf * 64 * ATD;

        // S = Q K^T  (m16 x n64 x k64)
        float S[8][4];
#pragma unroll
        for (int nf = 0; nf < 8; nf++)
#pragma unroll
            for (int t = 0; t < 4; t++) S[nf][t] = 0.f;

#pragma unroll
        for (int s = 0; s < 4; s++) {
            uint32_t af[4];
            ldsm_x4(af, sptr(Qs + (warp * 16 + a_row) * ATD + s * 16 + a_col));
#pragma unroll
            for (int np = 0; np < 4; np++) {
                uint32_t bf[4];
                int row = np * 16 + (lane & 7) + ((lane & 16) >> 1);
                int col = s * 16 + (lane & 8);
                ldsm_x4(bf, sptr(Kb + row * ATD + col));
                mma_f16(S[np * 2],     af, bf[0], bf[1]);
                mma_f16(S[np * 2 + 1], af, bf[2], bf[3]);
            }
        }

        if (kt == qi) {   // diagonal: causal mask
#pragma unroll
            for (int nf = 0; nf < 8; nf++) {
                int c  = nf * 8 + 2 * tig;
                int r0 = warp * 16 + g, r1 = r0 + 8;
                if (c     > r0) S[nf][0] = -INFINITY;
                if (c + 1 > r0) S[nf][1] = -INFINITY;
                if (c     > r1) S[nf][2] = -INFINITY;
                if (c + 1 > r1) S[nf][3] = -INFINITY;
            }
        }

        // online softmax (rows g, g+8; 4 lanes/row -> xor 1,2)
#pragma unroll
        for (int r = 0; r < 2; r++) {
            float mx = -INFINITY;
#pragma unroll
            for (int nf = 0; nf < 8; nf++)
                mx = fmaxf(mx, fmaxf(S[nf][2 * r], S[nf][2 * r + 1]));
            mx = fmaxf(mx, __shfl_xor_sync(0xffffffffu, mx, 1));
            mx = fmaxf(mx, __shfl_xor_sync(0xffffffffu, mx, 2));
            float mn = fmaxf(m_i[r], mx);
            float alpha = __expf(m_i[r] - mn);
            float rs = 0.f;
#pragma unroll
            for (int nf = 0; nf < 8; nf++) {
                float p0 = __expf(S[nf][2 * r] - mn);
                float p1 = __expf(S[nf][2 * r + 1] - mn);
                S[nf][2 * r] = p0; S[nf][2 * r + 1] = p1;
                rs += p0 + p1;
            }
            rs += __shfl_xor_sync(0xffffffffu, rs, 1);
            rs += __shfl_xor_sync(0xffffffffu, rs, 2);
            l_i[r] = l_i[r] * alpha + rs;
            m_i[r] = mn;
#pragma unroll
            for (int nf = 0; nf < 8; nf++) {
                Oa[nf][2 * r]     *= alpha;
                Oa[nf][2 * r + 1] *= alpha;
            }
        }

        // stage P as fp16 (warp-private rows)
#pragma unroll
        for (int nf = 0; nf < 8; nf++) {
            *(__half2*)&Ps[(warp * 16 + g) * ATD + nf * 8 + 2 * tig] =
                __floats2half2_rn(S[nf][0], S[nf][1]);
            *(__half2*)&Ps[(warp * 16 + g + 8) * ATD + nf * 8 + 2 * tig] =
                __floats2half2_rn(S[nf][2], S[nf][3]);
        }
        __syncwarp();

        // O += P V   (m16 x n64 x k64), V via trans ldmatrix
#pragma unroll
        for (int s = 0; s < 4; s++) {
            uint32_t af[4];
            ldsm_x4(af, sptr(Ps + (warp * 16 + a_row) * ATD + s * 16 + a_col));
#pragma unroll
            for (int np = 0; np < 4; np++) {
                uint32_t bf[4];
                int row = s * 16 + (lane & 7) + (lane & 8);
                int col = np * 16 + ((lane & 16) >> 1);
                ldsm_x4t(bf, sptr(Vb + row * ATD + col));
                mma_f16(Oa[np * 2],     af, bf[0], bf[1]);
                mma_f16(Oa[np * 2 + 1], af, bf[2], bf[3]);
            }
        }
        __syncthreads();
        buf ^= 1;
    }

    __half* ob = o + (size_t)b * NM * ND + h * NHD;
#pragma unroll
    for (int r = 0; r < 2; r++) {
        float inv = 1.f / l_i[r];
        int row = q0 + warp * 16 + g + r * 8;
#pragma unroll
        for (int nf = 0; nf < 8; nf++)
            *(__half2*)(ob + (size_t)row * ND + nf * 8 + 2 * tig) =
                __floats2half2_rn(Oa[nf][2 * r] * inv, Oa[nf][2 * r + 1] * inv);
    }
}

// ===========================================================================
extern "C" void kernel_launch(void* const* d_in, const int* in_sizes, int n_in,
                              void* d_out, int out_size)
{
    const float* x   = (const float*)d_in[0];
    const float* wq  = (const float*)d_in[1];
    const float* wk  = (const float*)d_in[2];
    const float* wv  = (const float*)d_in[3];
    const float* ipw = (const float*)d_in[4];
    const float* ipb = (const float*)d_in[5];
    const float* ow  = (const float*)d_in[6];
    const float* ob  = (const float*)d_in[7];
    float* out = (float*)d_out;

    __half *hx, *hwq, *hwk, *hwv, *hipw, *how, *hq, *hk, *hv, *hqh, *hkh, *hvh, *ho;
    cudaGetSymbolAddress((void**)&hx,  h_x);
    cudaGetSymbolAddress((void**)&hwq, h_wq);
    cudaGetSymbolAddress((void**)&hwk, h_wk);
    cudaGetSymbolAddress((void**)&hwv, h_wv);
    cudaGetSymbolAddress((void**)&hipw, h_ipw);
    cudaGetSymbolAddress((void**)&how, h_ow);
    cudaGetSymbolAddress((void**)&hq,  h_q);
    cudaGetSymbolAddress((void**)&hk,  h_k);
    cudaGetSymbolAddress((void**)&hv,  h_v);
    cudaGetSymbolAddress((void**)&hqh, h_qh);
    cudaGetSymbolAddress((void**)&hkh, h_kh);
    cudaGetSymbolAddress((void**)&hvh, h_vh);
    cudaGetSymbolAddress((void**)&ho,  h_o);

    const int gemm_smem = 2 * 2 * 128 * GLD * 2;   // 73728 bytes
    cudaFuncSetAttribute(gemm_f16_kernel<1>,
                         cudaFuncAttributeMaxDynamicSharedMemorySize, gemm_smem);
    cudaFuncSetAttribute(gemm_f16_kernel<2>,
                         cudaFuncAttributeMaxDynamicSharedMemorySize, gemm_smem);
    cudaFuncSetAttribute(gemm_f16_kernel<3>,
                         cudaFuncAttributeMaxDynamicSharedMemorySize, gemm_smem);
    cudaFuncSetAttribute(attn_f16_kernel,
                         cudaFuncAttributeMaxDynamicSharedMemorySize, ASM_TOT);

    init_theta_kernel<<<1, 512>>>();

    // fp32 -> fp16 converts
    auto cvt = [&](const float* src, __half* dst, int n) {
        int n8 = n / 8;
        f2h_kernel<<<(n8 + 255) / 256, 256>>>((const float4*)src, (uint2*)dst, n8);
    };
    cvt(x,   hx,   NTOK * ND);
    cvt(wq,  hwq,  ND * ND);
    cvt(wk,  hwk,  ND * ND);
    cvt(wv,  hwv,  ND * ND);
    cvt(ipw, hipw, 3 * ND * ND);
    cvt(ow,  how,  ND * ND);

    dim3 gb(8, 32), tb(256);
    // QKV projections with fused RoPE epilogue (fp16 out)
    gemm_f16_kernel<2><<<gb, tb, gemm_smem>>>(hx, hwq, nullptr, hq, nullptr, 1.f);
    gemm_f16_kernel<2><<<gb, tb, gemm_smem>>>(hx, hwk, nullptr, hk, nullptr, 1.f);
    gemm_f16_kernel<2><<<gb, tb, gemm_smem>>>(hx, hwv, nullptr, hv, nullptr, 1.f);
    // in_proj (bias fused; qh additionally scaled by 1/sqrt(hd)=0.125)
    gemm_f16_kernel<1><<<gb, tb, gemm_smem>>>(hq, hipw,                 ipb,        hqh, nullptr, 0.125f);
    gemm_f16_kernel<1><<<gb, tb, gemm_smem>>>(hk, hipw + 1024 * 1024,   ipb + 1024, hkh, nullptr, 1.f);
    gemm_f16_kernel<1><<<gb, tb, gemm_smem>>>(hv, hipw + 2 * 1024 * 1024, ipb + 2048, hvh, nullptr, 1.f);
    // causal flash attention (fp16 out)
    attn_f16_kernel<<<dim3(NM / 64, NH, NB), 128, ASM_TOT>>>(hqh, hkh, hvh, ho);
    // output projection -> fp32 + bias
    gemm_f16_kernel<3><<<gb, tb, gemm_smem>>>(ho, how, ob, nullptr, out, 1.f);
}